// round 1
// baseline (speedup 1.0000x reference)
#include <cuda_runtime.h>
#include <math.h>

#define N_NODES 256
#define F_IN    128
#define F_OUT   64
#define BT_TOTAL 512

// padded smem strides (floats) to kill bank conflicts on the a-operand reads
#define SH_STRIDE 132   // (r*132 + k) % 32 = (4r + k) % 32 -> 8 consecutive rows hit distinct banks
#define SA_STRIDE 260   // same property

// ---- dynamic smem layout (float offsets) ----
// sWh  [256][64]              @ 0          (16384 floats)
// region2 (16640 floats)      @ 16384:
//    phase1: sH [64][132] (8448) then sW [128][64] (8192)  = 16640
//    phase3: sA [64][260]                                   = 16640
// sWh1 [256]                  @ 33024
// sWh2 [256]                  @ 33280
// rmax [256]                  @ 33536
// rinv [256]                  @ 33792
#define OFF_SWH   0
#define OFF_R2    16384
#define OFF_SW    (OFF_R2 + 8448)
#define OFF_SWH1  (OFF_R2 + 16640)
#define OFF_SWH2  (OFF_SWH1 + 256)
#define OFF_RMAX  (OFF_SWH2 + 256)
#define OFF_RINV  (OFF_RMAX + 256)
#define SMEM_FLOATS (OFF_RINV + 256)
#define SMEM_BYTES  (SMEM_FLOATS * 4)   // 136192 bytes

__global__ __launch_bounds__(256, 1)
void gat_fused_kernel(const float* __restrict__ h,
                      const float* __restrict__ W,
                      const float* __restrict__ a,
                      const float* __restrict__ adj,
                      float* __restrict__ out)
{
    extern __shared__ float smem[];
    float* sWh   = smem + OFF_SWH;    // [256][64]
    float* sH    = smem + OFF_R2;     // [64][SH_STRIDE]   (phase 1)
    float* sW    = smem + OFF_SW;     // [128][64]         (phase 1)
    float* sA    = smem + OFF_R2;     // [64][SA_STRIDE]   (phase 3, aliases sH+sW)
    float* sWh1  = smem + OFF_SWH1;
    float* sWh2  = smem + OFF_SWH2;
    float* rmax  = smem + OFF_RMAX;
    float* rinv  = smem + OFF_RINV;

    const int tid  = threadIdx.x;
    const int bt   = blockIdx.x;
    const int lane = tid & 31;
    const int warp = tid >> 5;

    // 16x16 thread grid for 4x4 register tiling
    const int tc = tid & 15;       // col group
    const int tr = tid >> 4;       // row group
    const int c0 = tc * 4;
    const int lr0 = tr * 4;

    const float* hB = h + (size_t)bt * N_NODES * F_IN;

    // ---- load W into smem (row-major [128][64]) ----
    {
        const float4* Wsrc = reinterpret_cast<const float4*>(W);
        float4* Wdst = reinterpret_cast<float4*>(sW);
        #pragma unroll
        for (int idx = tid; idx < (F_IN * F_OUT) / 4; idx += 256)
            Wdst[idx] = Wsrc[idx];
    }

    // per-thread a1/a2 slices for this thread's 4 output cols
    float a1v[4], a2v[4];
    #pragma unroll
    for (int j = 0; j < 4; ++j) {
        a1v[j] = a[c0 + j];
        a2v[j] = a[F_OUT + c0 + j];
    }

    // ================= Phase 1: Wh = h @ W, plus Wh1/Wh2 =================
    for (int cb = 0; cb < N_NODES; cb += 64) {
        __syncthreads();  // previous chunk's sH reads done (also covers sW load 1st iter)
        // load 64x128 h chunk into sH (padded stride)
        {
            const float4* hsrc = reinterpret_cast<const float4*>(hB + cb * F_IN);
            #pragma unroll
            for (int idx = tid; idx < 2048; idx += 256) {
                int r  = idx >> 5;        // 32 float4 per row
                int c4 = idx & 31;
                *reinterpret_cast<float4*>(&sH[r * SH_STRIDE + c4 * 4]) = hsrc[idx];
            }
        }
        __syncthreads();

        float acc[4][4] = {};
        #pragma unroll 4
        for (int k = 0; k < F_IN; ++k) {
            float4 bv = *reinterpret_cast<const float4*>(&sW[k * F_OUT + c0]);
            float av0 = sH[(lr0 + 0) * SH_STRIDE + k];
            float av1 = sH[(lr0 + 1) * SH_STRIDE + k];
            float av2 = sH[(lr0 + 2) * SH_STRIDE + k];
            float av3 = sH[(lr0 + 3) * SH_STRIDE + k];
            acc[0][0] += av0 * bv.x; acc[0][1] += av0 * bv.y; acc[0][2] += av0 * bv.z; acc[0][3] += av0 * bv.w;
            acc[1][0] += av1 * bv.x; acc[1][1] += av1 * bv.y; acc[1][2] += av1 * bv.z; acc[1][3] += av1 * bv.w;
            acc[2][0] += av2 * bv.x; acc[2][1] += av2 * bv.y; acc[2][2] += av2 * bv.z; acc[2][3] += av2 * bv.w;
            acc[3][0] += av3 * bv.x; acc[3][1] += av3 * bv.y; acc[3][2] += av3 * bv.z; acc[3][3] += av3 * bv.w;
        }

        // write Wh tile + per-row partial dots with a1/a2
        float p1[4], p2[4];
        #pragma unroll
        for (int i = 0; i < 4; ++i) {
            int r = cb + lr0 + i;
            *reinterpret_cast<float4*>(&sWh[r * F_OUT + c0]) =
                make_float4(acc[i][0], acc[i][1], acc[i][2], acc[i][3]);
            p1[i] = acc[i][0] * a1v[0] + acc[i][1] * a1v[1] + acc[i][2] * a1v[2] + acc[i][3] * a1v[3];
            p2[i] = acc[i][0] * a2v[0] + acc[i][1] * a2v[1] + acc[i][2] * a2v[2] + acc[i][3] * a2v[3];
        }
        // reduce across the 16 col-group lanes (xor 8,4,2,1 stays inside the 16-lane half)
        #pragma unroll
        for (int off = 8; off > 0; off >>= 1) {
            #pragma unroll
            for (int i = 0; i < 4; ++i) {
                p1[i] += __shfl_xor_sync(0xffffffffu, p1[i], off);
                p2[i] += __shfl_xor_sync(0xffffffffu, p2[i], off);
            }
        }
        if (tc == 0) {
            #pragma unroll
            for (int i = 0; i < 4; ++i) {
                sWh1[cb + lr0 + i] = p1[i];
                sWh2[cb + lr0 + i] = p2[i];
            }
        }
    }
    __syncthreads();

    // ================= Phase 2: per-row softmax max & 1/sum =================
    // warp per row; 8 warps x 32 rows each
    for (int i = warp; i < N_NODES; i += 8) {
        const float s = sWh1[i];
        const float* adjrow = adj + i * N_NODES;
        float vals[8];
        #pragma unroll
        for (int q = 0; q < 8; ++q) {
            int j = lane + 32 * q;
            float ad = __ldg(adjrow + j);
            float e = s + sWh2[j];
            e = e > 0.0f ? e : 0.01f * e;
            vals[q] = (ad > 0.0f) ? e : -3.0e38f;
        }
        float m = vals[0];
        #pragma unroll
        for (int q = 1; q < 8; ++q) m = fmaxf(m, vals[q]);
        #pragma unroll
        for (int off = 16; off > 0; off >>= 1)
            m = fmaxf(m, __shfl_xor_sync(0xffffffffu, m, off));
        float sum = 0.0f;
        #pragma unroll
        for (int q = 0; q < 8; ++q)
            sum += (vals[q] > -1.0e38f) ? __expf(vals[q] - m) : 0.0f;
        #pragma unroll
        for (int off = 16; off > 0; off >>= 1)
            sum += __shfl_xor_sync(0xffffffffu, sum, off);
        if (lane == 0) {
            rmax[i] = m;
            rinv[i] = 1.0f / sum;
        }
    }
    __syncthreads();

    // ================= Phase 3: alpha tile + (alpha @ Wh) + ELU =================
    float* outB = out + (size_t)bt * N_NODES * F_OUT;
    for (int cb = 0; cb < N_NODES; cb += 64) {
        // fill alpha tile sA[64][256] (recompute p_ij)
        #pragma unroll
        for (int idx = tid; idx < 64 * 256; idx += 256) {
            int r = idx >> 8;
            int j = idx & 255;
            int gi = cb + r;
            float ad = __ldg(adj + gi * N_NODES + j);
            float p = 0.0f;
            if (ad > 0.0f) {
                float e = sWh1[gi] + sWh2[j];
                e = e > 0.0f ? e : 0.01f * e;
                p = __expf(e - rmax[gi]) * rinv[gi];
            }
            sA[r * SA_STRIDE + j] = p;
        }
        __syncthreads();

        float acc[4][4] = {};
        #pragma unroll 4
        for (int k = 0; k < N_NODES; ++k) {
            float4 bv = *reinterpret_cast<const float4*>(&sWh[k * F_OUT + c0]);
            float av0 = sA[(lr0 + 0) * SA_STRIDE + k];
            float av1 = sA[(lr0 + 1) * SA_STRIDE + k];
            float av2 = sA[(lr0 + 2) * SA_STRIDE + k];
            float av3 = sA[(lr0 + 3) * SA_STRIDE + k];
            acc[0][0] += av0 * bv.x; acc[0][1] += av0 * bv.y; acc[0][2] += av0 * bv.z; acc[0][3] += av0 * bv.w;
            acc[1][0] += av1 * bv.x; acc[1][1] += av1 * bv.y; acc[1][2] += av1 * bv.z; acc[1][3] += av1 * bv.w;
            acc[2][0] += av2 * bv.x; acc[2][1] += av2 * bv.y; acc[2][2] += av2 * bv.z; acc[2][3] += av2 * bv.w;
            acc[3][0] += av3 * bv.x; acc[3][1] += av3 * bv.y; acc[3][2] += av3 * bv.z; acc[3][3] += av3 * bv.w;
        }

        // ELU + store
        #pragma unroll
        for (int i = 0; i < 4; ++i) {
            int r = cb + lr0 + i;
            float4 v;
            float x;
            x = acc[i][0]; v.x = x > 0.0f ? x : expm1f(x);
            x = acc[i][1]; v.y = x > 0.0f ? x : expm1f(x);
            x = acc[i][2]; v.z = x > 0.0f ? x : expm1f(x);
            x = acc[i][3]; v.w = x > 0.0f ? x : expm1f(x);
            *reinterpret_cast<float4*>(&outB[r * F_OUT + c0]) = v;
        }
        __syncthreads();  // before next chunk overwrites sA
    }
}

extern "C" void kernel_launch(void* const* d_in, const int* in_sizes, int n_in,
                              void* d_out, int out_size)
{
    const float* h   = (const float*)d_in[0];   // (8,64,256,128)
    const float* W   = (const float*)d_in[1];   // (128,64)
    const float* a   = (const float*)d_in[2];   // (128,1)
    const float* adj = (const float*)d_in[3];   // (256,256)
    float* out = (float*)d_out;                 // (8,64,256,64)

    cudaFuncSetAttribute(gat_fused_kernel,
                         cudaFuncAttributeMaxDynamicSharedMemorySize, SMEM_BYTES);
    gat_fused_kernel<<<BT_TOTAL, 256, SMEM_BYTES>>>(h, W, a, adj, out);
}